// round 4
// baseline (speedup 1.0000x reference)
#include <cuda_runtime.h>
#include <cuda_bf16.h>

// Recall_53077205844588: masked mean of remapped `predicted` over gt!=0.
// predicted: [B=32, F=512, T=2048] fp32; gt: same shape int32 in {0,1}.
// result = sum_{gt!=0} predicted[b, f==0?1:f, t==0?1:t] / count, or 0 if count==0.
//
// Remap predicates (f==0 row, t==0 col for vector lane .x) are THREAD-INVARIANT
// under this mapping (iteration stride = 2^19 doesn't touch bits <19), so all
// index math is hoisted out of the streaming loop. Loop uses unroll 4 (the
// empirically best MLP operating point — unroll 8 regressed via L1tex-queue
// contention + occupancy loss) and __ldcs streaming loads (read-once data).

#define B_DIM 32
#define F_DIM 512
#define T_DIM 2048
#define N_ELEMS (B_DIM * F_DIM * T_DIM)       // 33,554,432
#define N_VEC   (N_ELEMS / 4)                 // 8,388,608 float4 groups
#define NBLOCKS 2048
#define NTHREADS 256
#define TOTAL_THREADS (NBLOCKS * NTHREADS)    // 524,288 = 2^19
#define ITERS (N_VEC / TOTAL_THREADS)         // 16 exact

__device__ float        g_partial_sum[NBLOCKS];
__device__ unsigned int g_partial_cnt[NBLOCKS];
__device__ unsigned int g_done_counter = 0;   // atomicInc wraps to 0 -> graph-replay safe

__device__ __forceinline__ void block_reduce_write(float v, unsigned int c,
                                                   float* out_s, unsigned int* out_c)
{
    #pragma unroll
    for (int off = 16; off > 0; off >>= 1) {
        v += __shfl_down_sync(0xffffffffu, v, off);
        c += __shfl_down_sync(0xffffffffu, c, off);
    }
    __shared__ float        s_sum[NTHREADS / 32];
    __shared__ unsigned int s_cnt[NTHREADS / 32];
    const int lane = threadIdx.x & 31;
    const int wid  = threadIdx.x >> 5;
    if (lane == 0) { s_sum[wid] = v; s_cnt[wid] = c; }
    __syncthreads();
    if (wid == 0) {
        float        bs = (lane < NTHREADS / 32) ? s_sum[lane] : 0.0f;
        unsigned int bc = (lane < NTHREADS / 32) ? s_cnt[lane] : 0u;
        #pragma unroll
        for (int off = 4; off > 0; off >>= 1) {
            bs += __shfl_down_sync(0xffffffffu, bs, off);
            bc += __shfl_down_sync(0xffffffffu, bc, off);
        }
        if (lane == 0) { *out_s = bs; *out_c = bc; }
    }
    __syncthreads();
}

__global__ __launch_bounds__(NTHREADS) void recall_fused_kernel(
    const float* __restrict__ pred,
    const int*   __restrict__ gt,
    float*       __restrict__ out)
{
    const int base = blockIdx.x * NTHREADS + threadIdx.x;   // 0 .. 2^19-1

    // Thread-invariant remap predicates:
    //   f==0 rows:  bits 9..17 of the float4 index v == those of base
    //   t==0 lane:  low 9 bits of v == low 9 bits of base
    const bool f0 = ((base >> 9) & (F_DIM - 1)) == 0;
    const bool t0 = (base & 511) == 0;

    // Row remap f==0 -> f=1: constant +T_DIM float offset (=T_DIM/4 float4s).
    const float4* pp = (const float4*)pred + base + (f0 ? (T_DIM / 4) : 0);
    const int4*   gp = (const int4*)gt + base;

    float        local_sum = 0.0f;
    unsigned int local_cnt = 0;

    #pragma unroll 4
    for (int it = 0; it < ITERS; it++) {
        float4 p = __ldcs(pp + (size_t)it * TOTAL_THREADS);
        int4   g = __ldcs(gp + (size_t)it * TOTAL_THREADS);

        // Column remap t==0 -> t'=1: lane .y of the same (row-remapped) vector.
        if (t0) p.x = p.y;

        if (g.x) { local_sum += p.x; local_cnt++; }
        if (g.y) { local_sum += p.y; local_cnt++; }
        if (g.z) { local_sum += p.z; local_cnt++; }
        if (g.w) { local_sum += p.w; local_cnt++; }
    }

    float        blk_sum;
    unsigned int blk_cnt;
    block_reduce_write(local_sum, local_cnt, &blk_sum, &blk_cnt);

    __shared__ bool s_is_last;
    if (threadIdx.x == 0) {
        g_partial_sum[blockIdx.x] = blk_sum;
        g_partial_cnt[blockIdx.x] = blk_cnt;
        __threadfence();
        unsigned int prev = atomicInc(&g_done_counter, NBLOCKS - 1);
        s_is_last = (prev == NBLOCKS - 1);
    }
    __syncthreads();

    if (s_is_last) {
        float        fs = 0.0f;
        unsigned int fc = 0;
        #pragma unroll
        for (int j = 0; j < NBLOCKS / NTHREADS; j++) {
            const int idx = j * NTHREADS + threadIdx.x;
            fs += g_partial_sum[idx];
            fc += g_partial_cnt[idx];
        }
        float        tot_sum;
        unsigned int tot_cnt;
        block_reduce_write(fs, fc, &tot_sum, &tot_cnt);
        if (threadIdx.x == 0) {
            out[0] = (tot_cnt > 0u) ? (tot_sum / (float)tot_cnt) : 0.0f;
        }
    }
}

extern "C" void kernel_launch(void* const* d_in, const int* in_sizes, int n_in,
                              void* d_out, int out_size)
{
    const float* pred = (const float*)d_in[0];
    const int*   gt   = (const int*)d_in[1];
    float*       out  = (float*)d_out;

    recall_fused_kernel<<<NBLOCKS, NTHREADS>>>(pred, gt, out);
}

// round 5
// speedup vs baseline: 1.0942x; 1.0942x over previous
#include <cuda_runtime.h>
#include <cuda_bf16.h>

// Recall_53077205844588: masked mean of remapped `predicted` over gt!=0.
// predicted: [B=32, F=512, T=2048] fp32; gt: same shape int32 in {0,1}.
// result = sum_{gt!=0} predicted[b, f==0?1:f, t==0?1:t] / count, or 0 if count==0.
//
// Contiguous-per-block mapping: block owns 4096 consecutive float4s, thread t
// iter i reads base + i*256 + t -> per-iter offsets i*4KB fit LDG immediates
// (no per-iteration address ALU, 2 base regs). Remap predicates resolve to:
//   f==0 rows: blocks with blockIdx%64==0, iterations 0..1 only (+512 float4 shift)
//   t==0 lane: t==0 threads, even iterations only (p.x <- p.y)
// __launch_bounds__(256, 8) pins regs<=32 (the R2-proven best occupancy point).

#define F_DIM 512
#define T_DIM 2048
#define N_VEC   8388608                       // total float4 groups
#define NTHREADS 256
#define VEC_PER_BLOCK 4096                    // 16 iters * 256 threads
#define NBLOCKS (N_VEC / VEC_PER_BLOCK)       // 2048
#define ITERS 16

__device__ float        g_partial_sum[NBLOCKS];
__device__ unsigned int g_partial_cnt[NBLOCKS];
__device__ unsigned int g_done_counter = 0;   // atomicInc wraps to 0 -> graph-replay safe

__device__ __forceinline__ void block_reduce_write(float v, unsigned int c,
                                                   float* out_s, unsigned int* out_c)
{
    #pragma unroll
    for (int off = 16; off > 0; off >>= 1) {
        v += __shfl_down_sync(0xffffffffu, v, off);
        c += __shfl_down_sync(0xffffffffu, c, off);
    }
    __shared__ float        s_sum[NTHREADS / 32];
    __shared__ unsigned int s_cnt[NTHREADS / 32];
    const int lane = threadIdx.x & 31;
    const int wid  = threadIdx.x >> 5;
    if (lane == 0) { s_sum[wid] = v; s_cnt[wid] = c; }
    __syncthreads();
    if (wid == 0) {
        float        bs = (lane < NTHREADS / 32) ? s_sum[lane] : 0.0f;
        unsigned int bc = (lane < NTHREADS / 32) ? s_cnt[lane] : 0u;
        #pragma unroll
        for (int off = 4; off > 0; off >>= 1) {
            bs += __shfl_down_sync(0xffffffffu, bs, off);
            bc += __shfl_down_sync(0xffffffffu, bc, off);
        }
        if (lane == 0) { *out_s = bs; *out_c = bc; }
    }
    __syncthreads();
}

__global__ __launch_bounds__(NTHREADS, 8) void recall_fused_kernel(
    const float* __restrict__ pred,
    const int*   __restrict__ gt,
    float*       __restrict__ out)
{
    const int tid  = threadIdx.x;
    const int base = blockIdx.x * VEC_PER_BLOCK + tid;      // float4 index of iter 0

    // Block covers global rows blockIdx*8 .. blockIdx*8+7 (each row = 512 float4).
    // f==0 (global row 0 of an image) hits only blocks with blockIdx%64==0, and
    // within them only local rows 0..1's data = iterations 0..1.
    const bool f0b = (blockIdx.x & 63) == 0;
    // t==0 for vector lane .x: (i*256 + t) % 512 == 0  ->  t==0 and i even.
    const bool t0b = (tid == 0);

    const float4* pp    = (const float4*)pred + base;
    const float4* pp_f0 = pp + (T_DIM / 4);                 // row f=0 -> f=1 (+512 float4)
    const int4*   gp    = (const int4*)gt + base;

    float        local_sum = 0.0f;
    unsigned int local_cnt = 0;

    #pragma unroll
    for (int i = 0; i < ITERS; i++) {
        const float4* src = (i < 2 && f0b) ? pp_f0 : pp;    // i<2 is compile-time
        float4 p = __ldcs(src + i * NTHREADS);              // offset i*4KB: immediate
        int4   g = __ldcs(gp  + i * NTHREADS);

        if (((i & 1) == 0) && t0b) p.x = p.y;               // col remap t==0 -> t'=1

        if (g.x) { local_sum += p.x; local_cnt++; }
        if (g.y) { local_sum += p.y; local_cnt++; }
        if (g.z) { local_sum += p.z; local_cnt++; }
        if (g.w) { local_sum += p.w; local_cnt++; }
    }

    float        blk_sum;
    unsigned int blk_cnt;
    block_reduce_write(local_sum, local_cnt, &blk_sum, &blk_cnt);

    __shared__ bool s_is_last;
    if (threadIdx.x == 0) {
        g_partial_sum[blockIdx.x] = blk_sum;
        g_partial_cnt[blockIdx.x] = blk_cnt;
        __threadfence();
        unsigned int prev = atomicInc(&g_done_counter, NBLOCKS - 1);
        s_is_last = (prev == NBLOCKS - 1);
    }
    __syncthreads();

    if (s_is_last) {
        float        fs = 0.0f;
        unsigned int fc = 0;
        #pragma unroll
        for (int j = 0; j < NBLOCKS / NTHREADS; j++) {
            const int idx = j * NTHREADS + threadIdx.x;
            fs += g_partial_sum[idx];
            fc += g_partial_cnt[idx];
        }
        float        tot_sum;
        unsigned int tot_cnt;
        block_reduce_write(fs, fc, &tot_sum, &tot_cnt);
        if (threadIdx.x == 0) {
            out[0] = (tot_cnt > 0u) ? (tot_sum / (float)tot_cnt) : 0.0f;
        }
    }
}

extern "C" void kernel_launch(void* const* d_in, const int* in_sizes, int n_in,
                              void* d_out, int out_size)
{
    const float* pred = (const float*)d_in[0];
    const int*   gt   = (const int*)d_in[1];
    float*       out  = (float*)d_out;

    recall_fused_kernel<<<NBLOCKS, NTHREADS>>>(pred, gt, out);
}